// round 8
// baseline (speedup 1.0000x reference)
#include <cuda_runtime.h>

// Problem constants (fixed by setup_inputs)
#define NN 256
#define MM 2
#define TT 300
#define VV 25
#define CC 3
#define DD 256
#define KK 5
#define TOPK 64
#define ROWS (NN * MM * TT)          // 153600
#define SEL_ELEMS (NN * CC * TOPK * VV * MM)  // 2457600
#define EPSF 1e-8f

// Scratch (no allocation allowed -> __device__ globals)
__device__ float g_sums[KK * DD];
__device__ int   g_counts[KK];
__device__ float g_mean[KK * DD];
__device__ float g_inter[KK];
__device__ float g_Sb;
__device__ float g_Sw;
__device__ float g_score[ROWS];      // per-row frame score (no zeroing needed)
__device__ int   g_idx[NN * TOPK];

// ---------------------------------------------------------------- zero scratch
// only sums/counts/Sw/Sb need zeroing now (1287 elements) -> 1 block
__global__ void k_zero() {
    int tid = threadIdx.x;
#pragma unroll
    for (int i = tid; i < KK * DD; i += 256) g_sums[i] = 0.0f;
    if (tid < KK) g_counts[tid] = 0;
    if (tid == 0) { g_Sw = 0.0f; g_Sb = 0.0f; }
}

// ------------------------------------------------- per-class sums + counts
// 1200 blocks x 256 thr. Thread = (row-lane rl in 0..3) x (col-float4 c in 0..63).
// Register per-class accumulators; label is warp-uniform -> uniform branches.
#define SEG_R 128
__global__ void __launch_bounds__(256) k_segsum(const float* __restrict__ xT,
                                                const int* __restrict__ labels) {
    __shared__ int   slbl[SEG_R];
    __shared__ float4 sacc[KK][4][64];   // 20 KB
    int tid = threadIdx.x;
    int c  = tid & 63;
    int rl = tid >> 6;
    int r0 = blockIdx.x * SEG_R;
    if (tid < SEG_R) slbl[tid] = labels[r0 + tid];
    __syncthreads();

    float4 a0 = {0,0,0,0}, a1 = {0,0,0,0}, a2 = {0,0,0,0}, a3 = {0,0,0,0}, a4 = {0,0,0,0};
    const float4* p = ((const float4*)xT) + (size_t)r0 * 64 + c;

#define ACC4(A, V) { A.x += V.x; A.y += V.y; A.z += V.z; A.w += V.w; }
#pragma unroll
    for (int i = 0; i < 8; i++) {
        float4 v[4];
        int    l[4];
#pragma unroll
        for (int u = 0; u < 4; u++) {
            int r = rl + 16 * i + 4 * u;
            v[u] = __ldcs(&p[(size_t)r * 64]);
            l[u] = slbl[r];
        }
#pragma unroll
        for (int u = 0; u < 4; u++) {
            if      (l[u] == 0) ACC4(a0, v[u])
            else if (l[u] == 1) ACC4(a1, v[u])
            else if (l[u] == 2) ACC4(a2, v[u])
            else if (l[u] == 3) ACC4(a3, v[u])
            else                ACC4(a4, v[u])
        }
    }

    sacc[0][rl][c] = a0; sacc[1][rl][c] = a1; sacc[2][rl][c] = a2;
    sacc[3][rl][c] = a3; sacc[4][rl][c] = a4;
    __syncthreads();

    if (rl == 0) {
#pragma unroll
        for (int k = 0; k < KK; k++) {
            float4 s = sacc[k][0][c];
            float4 s1 = sacc[k][1][c], s2 = sacc[k][2][c], s3 = sacc[k][3][c];
            s.x += s1.x + s2.x + s3.x;
            s.y += s1.y + s2.y + s3.y;
            s.z += s1.z + s2.z + s3.z;
            s.w += s1.w + s2.w + s3.w;
            float* dst = &g_sums[k * DD + c * 4];
            atomicAdd(dst + 0, s.x); atomicAdd(dst + 1, s.y);
            atomicAdd(dst + 2, s.z); atomicAdd(dst + 3, s.w);
        }
    }
    if (tid < KK) {
        int cnt = 0;
#pragma unroll 8
        for (int r = 0; r < SEG_R; r++) cnt += (slbl[r] == tid);
        atomicAdd(&g_counts[tid], cnt);
    }
}

// ------------------------------------ class means, overall mean, inter, Sb
__global__ void k_finalize() {
    __shared__ float red[DD];
    int tid = threadIdx.x;
    float c[KK];
    float tot = 0.0f;
#pragma unroll
    for (int k = 0; k < KK; k++) { c[k] = (float)g_counts[k]; tot += c[k]; }

    float m[KK];
    float sum_all = 0.0f;
#pragma unroll
    for (int k = 0; k < KK; k++) {
        float sk = g_sums[k * DD + tid];
        sum_all += sk;
        m[k] = sk / fmaxf(c[k], 1.0f);
        g_mean[k * DD + tid] = m[k];
    }
    float ov = sum_all / tot;   // overall mean, dim = tid

    float Sb = 0.0f;
    for (int k = 0; k < KK; k++) {
        float d = m[k] - ov;
        red[tid] = d * d;
        __syncthreads();
        for (int s = DD / 2; s > 0; s >>= 1) {
            if (tid < s) red[tid] += red[tid + s];
            __syncthreads();
        }
        if (tid == 0) { g_inter[k] = red[0]; Sb += c[k] * red[0]; }
        __syncthreads();
    }
    if (tid == 0) g_Sb = Sb;
}

// ----------------------------- intra distances, Sw, frame scores
// 4800 blocks x 256 thr; class means staged in smem; each warp handles 4 rows.
// Writes per-row score (no atomics); Sw via one atomic per block.
__global__ void __launch_bounds__(256) k_intra(const float* __restrict__ xT,
                                               const int* __restrict__ labels) {
    __shared__ float smean[KK * DD];
    __shared__ float sinter[KK];
    __shared__ float swv[8];
    int tid  = threadIdx.x;
    int warp = tid >> 5;
    int lane = tid & 31;

#pragma unroll
    for (int i = tid; i < KK * DD; i += 256) smean[i] = g_mean[i];
    if (tid < KK) sinter[tid] = g_inter[tid];
    __syncthreads();

    int base = blockIdx.x * 32 + warp * 4;   // 4 rows per warp

    float acc[4];
    int lbl[4];
#pragma unroll
    for (int rr = 0; rr < 4; rr++) {
        int row = base + rr;
        lbl[rr] = labels[row];
        const float4* rp = (const float4*)(xT + (size_t)row * DD);
        const float4* mp = (const float4*)(smean + lbl[rr] * DD);
        float4 a  = __ldcs(&rp[lane]);
        float4 a2 = __ldcs(&rp[lane + 32]);
        float4 b  = mp[lane];
        float4 b2 = mp[lane + 32];
        float d0 = a.x - b.x,   d1 = a.y - b.y,   d2 = a.z - b.z,   d3 = a.w - b.w;
        float e0 = a2.x - b2.x, e1 = a2.y - b2.y, e2 = a2.z - b2.z, e3 = a2.w - b2.w;
        acc[rr] = d0*d0 + d1*d1 + d2*d2 + d3*d3 + e0*e0 + e1*e1 + e2*e2 + e3*e3;
    }

#pragma unroll
    for (int rr = 0; rr < 4; rr++) {
#pragma unroll
        for (int o = 16; o > 0; o >>= 1)
            acc[rr] += __shfl_down_sync(0xffffffffu, acc[rr], o);
    }

    if (lane == 0) {
        float sw4 = 0.0f;
#pragma unroll
        for (int rr = 0; rr < 4; rr++) {
            int row = base + rr;
            g_score[row] = sinter[lbl[rr]] / (acc[rr] + EPSF);
            sw4 += acc[rr];
        }
        swv[warp] = sw4;
    }
    __syncthreads();
    if (tid == 0) {
        float s = 0.0f;
#pragma unroll
        for (int w = 0; w < 8; w++) s += swv[w];
        atomicAdd(&g_Sw, s);
    }
}

// ------------------------- per-row top-64 of VF[256][300], sorted ascending
// one block (256 thr) per row; bitonic sort of 512 (pad -inf), JAX tie-break:
// equal values -> lower index first. VF built from per-row scores (mean over M).
// Also writes the scalar loss (block 0).
__global__ void k_topk(float* __restrict__ out, int has_loss) {
    __shared__ float sv[512];
    __shared__ int   si[512];
    int n = blockIdx.x;
    int tid = threadIdx.x;

    if (n == 0 && tid == 0 && has_loss) out[0] = g_Sw / (g_Sb + EPSF);

#pragma unroll
    for (int i = tid; i < 512; i += 256) {
        if (i < TT) {
            float s0 = g_score[(n * MM + 0) * TT + i];
            float s1 = g_score[(n * MM + 1) * TT + i];
            sv[i] = 0.5f * (s0 + s1);
            si[i] = i;
        } else {
            sv[i] = -__int_as_float(0x7f800000); si[i] = 1 << 30;
        }
    }

    // descending-by-value bitonic sort (tie: lower index first)
    for (int k = 2; k <= 512; k <<= 1) {
        for (int j = k >> 1; j > 0; j >>= 1) {
            __syncthreads();
#pragma unroll
            for (int i = tid; i < 512; i += 256) {
                int ixj = i ^ j;
                if (ixj > i) {
                    float av = sv[i], bv = sv[ixj];
                    int   ai = si[i], bi = si[ixj];
                    bool pre = (av > bv) || (av == bv && ai < bi); // a before b in target order
                    bool up  = ((i & k) == 0);
                    if (up ? !pre : pre) {
                        sv[i] = bv; sv[ixj] = av;
                        si[i] = bi; si[ixj] = ai;
                    }
                }
            }
        }
    }
    __syncthreads();

    // ascending sort of the 64 winning indices
    for (int k = 2; k <= TOPK; k <<= 1) {
        for (int j = k >> 1; j > 0; j >>= 1) {
            __syncthreads();
            if (tid < TOPK) {
                int i = tid, ixj = i ^ j;
                if (ixj > i) {
                    int a = si[i], b = si[ixj];
                    bool up = ((i & k) == 0);
                    if (up ? (a > b) : (a < b)) { si[i] = b; si[ixj] = a; }
                }
            }
        }
    }
    __syncthreads();
    if (tid < TOPK) g_idx[n * TOPK + tid] = si[tid];
}

// --------------------------------------------- gather selected frames from x
// each thread moves one float2 (reads 8B-aligned; output may be misaligned
// by the loss scalar, so stores are scalar)
__global__ void __launch_bounds__(256) k_gather(const float* __restrict__ x,
                                                float* __restrict__ sel) {
    int o2 = blockIdx.x * blockDim.x + threadIdx.x;      // < 1228800 exactly
    int inner2 = o2 % (VV * MM / 2);                      // 25 float2 per segment
    int j = (o2 / (VV * MM / 2)) % TOPK;
    int c = (o2 / (VV * MM / 2 * TOPK)) % CC;
    int n =  o2 / (VV * MM / 2 * TOPK * CC);
    int t = g_idx[n * TOPK + j];
    const float2* src = (const float2*)x;
    float2 v = __ldcs(&src[((size_t)(n * CC + c) * TT + t) * (VV * MM / 2) + inner2]);
    sel[2 * o2]     = v.x;
    sel[2 * o2 + 1] = v.y;
}

// ============================================================================
extern "C" void kernel_launch(void* const* d_in, const int* in_sizes, int n_in,
                              void* d_out, int out_size) {
    const float* x      = (const float*)d_in[0];   // [256,3,300,25,2]
    const float* xT     = (const float*)d_in[1];   // [153600,256]
    const int*   labels = (const int*)d_in[2];     // [153600]
    (void)in_sizes; (void)n_in;

    float* out = (float*)d_out;
    int off = out_size - SEL_ELEMS;                // expected 1 (loss scalar first)
    if (off < 0) off = 0;
    float* sel = out + off;

    k_zero<<<1, 256>>>();
    k_segsum<<<ROWS / SEG_R, 256>>>(xT, labels);
    k_finalize<<<1, 256>>>();
    k_intra<<<ROWS / 32, 256>>>(xT, labels);
    k_topk<<<NN, 256>>>(out, off);
    k_gather<<<SEL_ELEMS / 2 / 256, 256>>>(x, sel);
}

// round 9
// speedup vs baseline: 1.2622x; 1.2622x over previous
#include <cuda_runtime.h>

// Problem constants (fixed by setup_inputs)
#define NN 256
#define MM 2
#define TT 300
#define VV 25
#define CC 3
#define DD 256
#define KK 5
#define TOPK 64
#define ROWS (NN * MM * TT)          // 153600
#define SEL_ELEMS (NN * CC * TOPK * VV * MM)  // 2457600
#define EPSF 1e-8f

// Scratch (no allocation allowed -> __device__ globals)
__device__ float g_sums[KK * DD];
__device__ int   g_counts[KK];
__device__ float g_mean[KK * DD];
__device__ float g_inter[KK];
__device__ float g_Sb;
__device__ float g_Sw;
__device__ float g_score[ROWS];      // per-row frame score (no zeroing needed)
__device__ int   g_idx[NN * TOPK];

// ---------------------------------------------------------------- zero scratch
__global__ void k_zero() {
    int tid = threadIdx.x;
#pragma unroll
    for (int i = tid; i < KK * DD; i += 256) g_sums[i] = 0.0f;
    if (tid < KK) g_counts[tid] = 0;
    if (tid == 0) { g_Sw = 0.0f; g_Sb = 0.0f; }
}

// ------------------------------------------------- per-class sums + counts
// 600 blocks x 256 thr, 256 rows/block. Thread = (row-lane rl 0..3) x (float4-col c 0..63).
// Indexed smem float4 RMW: one LDS.128+4FADD+STS.128 per value, label warp-uniform
// (r independent of lane) -> no divergence, no predication bloat, conflict-free smem.
#define SEG_R 256
__global__ void __launch_bounds__(256) k_segsum(const float* __restrict__ xT,
                                                const int* __restrict__ labels) {
    __shared__ int    slbl[SEG_R];
    __shared__ float4 sacc[4][KK][64];   // 20 KB
    int tid = threadIdx.x;
    int c  = tid & 63;
    int rl = tid >> 6;
    int r0 = blockIdx.x * SEG_R;

#pragma unroll
    for (int k = 0; k < KK; k++) sacc[rl][k][c] = make_float4(0.f, 0.f, 0.f, 0.f);
    slbl[tid] = labels[r0 + tid];
    __syncthreads();

    const float4* p = ((const float4*)xT) + (size_t)r0 * 64 + c;

    for (int i = 0; i < 16; i++) {
        float4 v[4];
        int    l[4];
#pragma unroll
        for (int u = 0; u < 4; u++) {
            int r = rl + 16 * i + 4 * u;
            v[u] = __ldcs(&p[(size_t)r * 64]);
            l[u] = slbl[r];
        }
#pragma unroll
        for (int u = 0; u < 4; u++) {
            float4 s = sacc[rl][l[u]][c];
            s.x += v[u].x; s.y += v[u].y; s.z += v[u].z; s.w += v[u].w;
            sacc[rl][l[u]][c] = s;
        }
    }
    __syncthreads();

    if (rl == 0) {   // 64 threads flush
#pragma unroll
        for (int k = 0; k < KK; k++) {
            float4 s0 = sacc[0][k][c], s1 = sacc[1][k][c];
            float4 s2 = sacc[2][k][c], s3 = sacc[3][k][c];
            float sx = s0.x + s1.x + s2.x + s3.x;
            float sy = s0.y + s1.y + s2.y + s3.y;
            float sz = s0.z + s1.z + s2.z + s3.z;
            float sw = s0.w + s1.w + s2.w + s3.w;
            float* dst = &g_sums[k * DD + c * 4];
            atomicAdd(dst + 0, sx); atomicAdd(dst + 1, sy);
            atomicAdd(dst + 2, sz); atomicAdd(dst + 3, sw);
        }
    }
    if (tid < KK) {
        int cnt = 0;
#pragma unroll 8
        for (int r = 0; r < SEG_R; r++) cnt += (slbl[r] == tid);
        atomicAdd(&g_counts[tid], cnt);
    }
}

// ------------------------------------ class means, overall mean, inter, Sb
__global__ void k_finalize() {
    __shared__ float red[DD];
    int tid = threadIdx.x;
    float c[KK];
    float tot = 0.0f;
#pragma unroll
    for (int k = 0; k < KK; k++) { c[k] = (float)g_counts[k]; tot += c[k]; }

    float m[KK];
    float sum_all = 0.0f;
#pragma unroll
    for (int k = 0; k < KK; k++) {
        float sk = g_sums[k * DD + tid];
        sum_all += sk;
        m[k] = sk / fmaxf(c[k], 1.0f);
        g_mean[k * DD + tid] = m[k];
    }
    float ov = sum_all / tot;   // overall mean, dim = tid

    float Sb = 0.0f;
    for (int k = 0; k < KK; k++) {
        float d = m[k] - ov;
        red[tid] = d * d;
        __syncthreads();
        for (int s = DD / 2; s > 0; s >>= 1) {
            if (tid < s) red[tid] += red[tid + s];
            __syncthreads();
        }
        if (tid == 0) { g_inter[k] = red[0]; Sb += c[k] * red[0]; }
        __syncthreads();
    }
    if (tid == 0) g_Sb = Sb;
}

// ----------------------------- intra distances, Sw, frame scores
// 4800 blocks x 256 thr; class means staged in smem; each warp handles 4 rows.
__global__ void __launch_bounds__(256) k_intra(const float* __restrict__ xT,
                                               const int* __restrict__ labels) {
    __shared__ float smean[KK * DD];
    __shared__ float sinter[KK];
    __shared__ float swv[8];
    int tid  = threadIdx.x;
    int warp = tid >> 5;
    int lane = tid & 31;

#pragma unroll
    for (int i = tid; i < KK * DD; i += 256) smean[i] = g_mean[i];
    if (tid < KK) sinter[tid] = g_inter[tid];
    __syncthreads();

    int base = blockIdx.x * 32 + warp * 4;   // 4 rows per warp

    float acc[4];
    int lbl[4];
#pragma unroll
    for (int rr = 0; rr < 4; rr++) {
        int row = base + rr;
        lbl[rr] = labels[row];
        const float4* rp = (const float4*)(xT + (size_t)row * DD);
        const float4* mp = (const float4*)(smean + lbl[rr] * DD);
        float4 a  = __ldcs(&rp[lane]);
        float4 a2 = __ldcs(&rp[lane + 32]);
        float4 b  = mp[lane];
        float4 b2 = mp[lane + 32];
        float d0 = a.x - b.x,   d1 = a.y - b.y,   d2 = a.z - b.z,   d3 = a.w - b.w;
        float e0 = a2.x - b2.x, e1 = a2.y - b2.y, e2 = a2.z - b2.z, e3 = a2.w - b2.w;
        acc[rr] = d0*d0 + d1*d1 + d2*d2 + d3*d3 + e0*e0 + e1*e1 + e2*e2 + e3*e3;
    }

#pragma unroll
    for (int rr = 0; rr < 4; rr++) {
#pragma unroll
        for (int o = 16; o > 0; o >>= 1)
            acc[rr] += __shfl_down_sync(0xffffffffu, acc[rr], o);
    }

    if (lane == 0) {
        float sw4 = 0.0f;
#pragma unroll
        for (int rr = 0; rr < 4; rr++) {
            int row = base + rr;
            g_score[row] = sinter[lbl[rr]] / (acc[rr] + EPSF);
            sw4 += acc[rr];
        }
        swv[warp] = sw4;
    }
    __syncthreads();
    if (tid == 0) {
        float s = 0.0f;
#pragma unroll
        for (int w = 0; w < 8; w++) s += swv[w];
        atomicAdd(&g_Sw, s);
    }
}

// ------------------------- per-row top-64 of VF[256][300], sorted ascending
// one block (256 thr) per row; bitonic sort of 512 (pad -inf), JAX tie-break:
// equal values -> lower index first. Also writes the scalar loss (block 0).
__global__ void k_topk(float* __restrict__ out, int has_loss) {
    __shared__ float sv[512];
    __shared__ int   si[512];
    int n = blockIdx.x;
    int tid = threadIdx.x;

    if (n == 0 && tid == 0 && has_loss) out[0] = g_Sw / (g_Sb + EPSF);

#pragma unroll
    for (int i = tid; i < 512; i += 256) {
        if (i < TT) {
            float s0 = g_score[(n * MM + 0) * TT + i];
            float s1 = g_score[(n * MM + 1) * TT + i];
            sv[i] = 0.5f * (s0 + s1);
            si[i] = i;
        } else {
            sv[i] = -__int_as_float(0x7f800000); si[i] = 1 << 30;
        }
    }

    // descending-by-value bitonic sort (tie: lower index first)
    for (int k = 2; k <= 512; k <<= 1) {
        for (int j = k >> 1; j > 0; j >>= 1) {
            __syncthreads();
#pragma unroll
            for (int i = tid; i < 512; i += 256) {
                int ixj = i ^ j;
                if (ixj > i) {
                    float av = sv[i], bv = sv[ixj];
                    int   ai = si[i], bi = si[ixj];
                    bool pre = (av > bv) || (av == bv && ai < bi); // a before b in target order
                    bool up  = ((i & k) == 0);
                    if (up ? !pre : pre) {
                        sv[i] = bv; sv[ixj] = av;
                        si[i] = bi; si[ixj] = ai;
                    }
                }
            }
        }
    }
    __syncthreads();

    // ascending sort of the 64 winning indices
    for (int k = 2; k <= TOPK; k <<= 1) {
        for (int j = k >> 1; j > 0; j >>= 1) {
            __syncthreads();
            if (tid < TOPK) {
                int i = tid, ixj = i ^ j;
                if (ixj > i) {
                    int a = si[i], b = si[ixj];
                    bool up = ((i & k) == 0);
                    if (up ? (a > b) : (a < b)) { si[i] = b; si[ixj] = a; }
                }
            }
        }
    }
    __syncthreads();
    if (tid < TOPK) g_idx[n * TOPK + tid] = si[tid];
}

// --------------------------------------------- gather selected frames from x
__global__ void __launch_bounds__(256) k_gather(const float* __restrict__ x,
                                                float* __restrict__ sel) {
    int o2 = blockIdx.x * blockDim.x + threadIdx.x;      // < 1228800 exactly
    int inner2 = o2 % (VV * MM / 2);                      // 25 float2 per segment
    int j = (o2 / (VV * MM / 2)) % TOPK;
    int c = (o2 / (VV * MM / 2 * TOPK)) % CC;
    int n =  o2 / (VV * MM / 2 * TOPK * CC);
    int t = g_idx[n * TOPK + j];
    const float2* src = (const float2*)x;
    float2 v = __ldcs(&src[((size_t)(n * CC + c) * TT + t) * (VV * MM / 2) + inner2]);
    sel[2 * o2]     = v.x;
    sel[2 * o2 + 1] = v.y;
}

// ============================================================================
extern "C" void kernel_launch(void* const* d_in, const int* in_sizes, int n_in,
                              void* d_out, int out_size) {
    const float* x      = (const float*)d_in[0];   // [256,3,300,25,2]
    const float* xT     = (const float*)d_in[1];   // [153600,256]
    const int*   labels = (const int*)d_in[2];     // [153600]
    (void)in_sizes; (void)n_in;

    float* out = (float*)d_out;
    int off = out_size - SEL_ELEMS;                // expected 1 (loss scalar first)
    if (off < 0) off = 0;
    float* sel = out + off;

    k_zero<<<1, 256>>>();
    k_segsum<<<ROWS / SEG_R, 256>>>(xT, labels);
    k_finalize<<<1, 256>>>();
    k_intra<<<ROWS / 32, 256>>>(xT, labels);
    k_topk<<<NN, 256>>>(out, off);
    k_gather<<<SEL_ELEMS / 2 / 256, 256>>>(x, sel);
}